// round 9
// baseline (speedup 1.0000x reference)
#include <cuda_runtime.h>
#include <math.h>
#include <stdint.h>

#define D 128
#define NRELS 16
#define MAXN 50000
#define MAXE 800000
#define MAXNT 400                     // max src tiles (BM=128)
#define NBMAX (NRELS * MAXNT)

// ---------------- scratch (__device__ globals: allocation-free rule) -------
__device__ float g_glog[(size_t)MAXN * NRELS];       // [n][r]
__device__ float g_h1[(size_t)MAXN * D];             // layer-0 out
__device__ float g_atf[(size_t)MAXN * D];            // h rounded to tf32
__device__ float g_wt[(size_t)NRELS * D * D];        // W^T tf32-rounded [r][e][d]
__device__ float g_lwt[(size_t)D * D];               // loop_w^T tf32-rounded
__device__ int   g_cnt[NBMAX];                        // bucket counts
__device__ int   g_cur[NBMAX];                        // bucket cursors
__device__ int   g_rp[NBMAX + 1];                     // bucket rowptr
__device__ int   g_perm[MAXE];                        // edge permutation

__device__ __forceinline__ float f2tf32f(float x) {
    uint32_t y;
    asm("cvt.rna.tf32.f32 %0, %1;" : "=r"(y) : "f"(x));
    return __uint_as_float(y);
}
__device__ __forceinline__ uint32_t smem_u32(const void* p) {
    uint32_t a;
    asm("{ .reg .u64 t; cvta.to.shared.u64 t, %1; cvt.u32.u64 %0, t; }"
        : "=r"(a) : "l"(p));
    return a;
}
__device__ __forceinline__ void cp16(uint32_t dst, const void* src, int srcBytes) {
    asm volatile("cp.async.cg.shared.global [%0], [%1], 16, %2;"
                 :: "r"(dst), "l"(src), "r"(srcBytes) : "memory");
}
#define CP_COMMIT() asm volatile("cp.async.commit_group;" ::: "memory")
#define CP_WAIT0()  asm volatile("cp.async.wait_group 0;" ::: "memory")

#define SROW_A 132
#define SROW_B 68
// ---------------- fused kernel SMEM layout (BM=128) ------------------------
#define FA_BYTES (128 * SROW_A * 4)        // 67584  A tile, full K
#define FB_CHUNK (128 * SROW_B * 4)        // 34816  B half-K chunk
#define FC_BYTES (128 * SROW_A * 4)        // 67584  C stage
#define FUSED_SMEM (FA_BYTES + 2 * FB_CHUNK + FC_BYTES)   // 204800

// ---------------------------------------------------------------------------
// FUSED: per CTA = one 128-row src tile; loops r = 0..15:
//   MMA (tf32, warp tile 32x64, 8 warps) -> C stage in SMEM -> scatter bucket
//   (r, tile): out[dst] += norm*sigmoid(glog)*Crow  via red.global.add.v4.
// B[r] double-buffered in half-K chunks via cp.async.
// ---------------------------------------------------------------------------
__global__ __launch_bounds__(256, 1)
void fused_gemm_scatter(const float* __restrict__ A, const float* __restrict__ B,
                        const int* __restrict__ src, const int* __restrict__ dst,
                        const int* __restrict__ rel, const float* __restrict__ norm,
                        float* __restrict__ out, int NT, int M)
{
    extern __shared__ char smem[];
    const uint32_t sA  = smem_u32(smem);
    const uint32_t sB0 = sA + FA_BYTES;
    const uint32_t sB1 = sB0 + FB_CHUNK;
    const uint32_t sC  = sB1 + FB_CHUNK;

    const int tid  = threadIdx.x;
    const int lane = tid & 31;
    const int wid  = tid >> 5;
    const int warp_m = wid >> 1;        // 0..3 (32 rows each)
    const int warp_n = wid & 1;         // 0..1 (64 cols each)
    const int g = lane >> 2;            // 0..7
    const int c = lane & 3;             // 0..3
    const int tile = blockIdx.x;
    const int mBase = tile * 128;
    const int nChunks = 2 * NRELS;

    // ---- stage A (128 x 128): 4096 16B chunks, 16 per thread --------------
#pragma unroll
    for (int it = 0; it < 16; it++) {
        int i = tid + it * 256;
        int row = i >> 5;
        int c4  = (i & 31) * 4;
        bool valid = (mBase + row) < M;
        const float* srcp = A + (valid ? ((size_t)(mBase + row) * D + c4) : 0);
        cp16(sA + (uint32_t)(row * SROW_A + c4) * 4, srcp, valid ? 16 : 0);
    }
    // ---- stage B chunk 0 ----------------------------------------------------
#pragma unroll
    for (int it = 0; it < 8; it++) {
        int i = tid + it * 256;
        int row = i >> 4;
        int c4  = (i & 15) * 4;
        cp16(sB0 + (uint32_t)(row * SROW_B + c4) * 4,
             B + (size_t)row * D + c4, 16);
    }
    CP_COMMIT();
    CP_WAIT0();
    __syncthreads();

    const uint32_t aBase = sA + (uint32_t)(warp_m * 32) * SROW_A * 4;

    float acc[2][8][4];

    for (int j = 0; j < nChunks; j++) {
        const uint32_t sCur = (j & 1) ? sB1 : sB0;

        if (j + 1 < nChunks) {   // prefetch next B chunk
            const uint32_t sNxt = (j & 1) ? sB0 : sB1;
            const int r1 = (j + 1) >> 1;
            const int h1 = ((j + 1) & 1) * 64;
            const float* Bc = B + (size_t)r1 * D * D + h1;
#pragma unroll
            for (int it = 0; it < 8; it++) {
                int i = tid + it * 256;
                int row = i >> 4;
                int c4  = (i & 15) * 4;
                cp16(sNxt + (uint32_t)(row * SROW_B + c4) * 4,
                     Bc + (size_t)row * D + c4, 16);
            }
            CP_COMMIT();
        }

        if (!(j & 1)) {
#pragma unroll
            for (int mi = 0; mi < 2; mi++)
#pragma unroll
                for (int ni = 0; ni < 8; ni++)
#pragma unroll
                    for (int f = 0; f < 4; f++) acc[mi][ni][f] = 0.f;
        }

        // ---- 8 k8-steps against this chunk ----------------------------------
        const int kbGlob = (j & 1) * 64;
        const uint32_t bBase = sCur + (uint32_t)(warp_n * 64) * SROW_B * 4;
#pragma unroll
        for (int kc = 0; kc < 8; kc++) {
            const int kbA = kbGlob + kc * 8;
            const int kbB = kc * 8;
            uint32_t af[2][4], bf[8][2];
#pragma unroll
            for (int mi = 0; mi < 2; mi++) {
                uint32_t a0 = aBase + (uint32_t)((mi * 16 + g) * SROW_A + kbA + c) * 4;
                asm volatile("ld.shared.b32 %0, [%1];"    : "=r"(af[mi][0]) : "r"(a0));
                asm volatile("ld.shared.b32 %0, [%1+16];" : "=r"(af[mi][2]) : "r"(a0));
                uint32_t a1 = a0 + 8u * SROW_A * 4u;
                asm volatile("ld.shared.b32 %0, [%1];"    : "=r"(af[mi][1]) : "r"(a1));
                asm volatile("ld.shared.b32 %0, [%1+16];" : "=r"(af[mi][3]) : "r"(a1));
            }
#pragma unroll
            for (int ni = 0; ni < 8; ni++) {
                uint32_t b0 = bBase + (uint32_t)((ni * 8 + g) * SROW_B + kbB + c) * 4;
                asm volatile("ld.shared.b32 %0, [%1];"    : "=r"(bf[ni][0]) : "r"(b0));
                asm volatile("ld.shared.b32 %0, [%1+16];" : "=r"(bf[ni][1]) : "r"(b0));
            }
#pragma unroll
            for (int mi = 0; mi < 2; mi++)
#pragma unroll
                for (int ni = 0; ni < 8; ni++) {
                    asm volatile(
                        "mma.sync.aligned.m16n8k8.row.col.f32.tf32.tf32.f32 "
                        "{%0,%1,%2,%3}, {%4,%5,%6,%7}, {%8,%9}, {%0,%1,%2,%3};\n"
                        : "+f"(acc[mi][ni][0]), "+f"(acc[mi][ni][1]),
                          "+f"(acc[mi][ni][2]), "+f"(acc[mi][ni][3])
                        : "r"(af[mi][0]), "r"(af[mi][1]),
                          "r"(af[mi][2]), "r"(af[mi][3]),
                          "r"(bf[ni][0]), "r"(bf[ni][1]));
                }
        }

        if (j & 1) {   // relation r complete
            const int r = j >> 1;
            // ---- stage C tile to SMEM --------------------------------------
#pragma unroll
            for (int mi = 0; mi < 2; mi++) {
                const int row0 = warp_m * 32 + mi * 16 + g;
                const int row1 = row0 + 8;
#pragma unroll
                for (int ni = 0; ni < 8; ni++) {
                    const int col = warp_n * 64 + ni * 8 + c * 2;
                    *(float2*)(smem + (sC - sA) + (size_t)(row0 * SROW_A + col) * 4) =
                        make_float2(acc[mi][ni][0], acc[mi][ni][1]);
                    *(float2*)(smem + (sC - sA) + (size_t)(row1 * SROW_A + col) * 4) =
                        make_float2(acc[mi][ni][2], acc[mi][ni][3]);
                }
            }
            __syncthreads();

            // ---- scatter edges of bucket (r, tile) -------------------------
            const int key = r * NT + tile;
            const int e0 = g_rp[key], e1 = g_rp[key + 1];
            for (int i = e0 + wid; i < e1; i += 8) {
                int e  = g_perm[i];
                int s  = __ldg(src + e);
                int dv = __ldg(dst + e);
                float nm = __ldg(norm + e);
                float gl = g_glog[(size_t)s * NRELS + r];
                float gc = nm / (1.f + expf(-gl));
                int dloc = s & 127;
                float4 v = *(const float4*)(smem + (sC - sA) +
                                            (size_t)(dloc * SROW_A + lane * 4) * 4);
                float* o = out + (size_t)dv * D + lane * 4;
                asm volatile("red.global.add.v4.f32 [%0], {%1,%2,%3,%4};"
                             :: "l"(o), "f"(v.x * gc), "f"(v.y * gc),
                                "f"(v.z * gc), "f"(v.w * gc)
                             : "memory");
            }
        }

        if (j + 1 < nChunks) {
            CP_WAIT0();
            __syncthreads();
        }
    }
}

// ---------------------------------------------------------------------------
// loop GEMM (BM=256, 512 threads, warp tile 64x32) — proven config from R5
// ---------------------------------------------------------------------------
#define SM_A_BYTES (256 * SROW_A * 4)
#define SM_BCHUNK  (128 * SROW_B * 4)
#define GEMM_SMEM  (SM_A_BYTES + 2 * SM_BCHUNK)

__global__ __launch_bounds__(512)
void gemm_loop(const float* __restrict__ A, const float* __restrict__ B,
               float* __restrict__ C0, int M, const float* __restrict__ bias)
{
    extern __shared__ char smem[];
    const uint32_t sA  = smem_u32(smem);
    const uint32_t sB0 = sA + SM_A_BYTES;
    const uint32_t sB1 = sB0 + SM_BCHUNK;

    const int tid  = threadIdx.x;
    const int lane = tid & 31;
    const int wid  = tid >> 5;
    const int warp_m = wid >> 2;
    const int warp_n = wid & 3;
    const int g = lane >> 2;
    const int c = lane & 3;
    const int mBase = blockIdx.x * 256;

#pragma unroll
    for (int it = 0; it < 16; it++) {
        int i = tid + it * 512;
        int row = i >> 5;
        int c4  = (i & 31) * 4;
        bool valid = (mBase + row) < M;
        const float* srcp = A + (valid ? ((size_t)(mBase + row) * D + c4) : 0);
        cp16(sA + (uint32_t)(row * SROW_A + c4) * 4, srcp, valid ? 16 : 0);
    }
#pragma unroll
    for (int it = 0; it < 4; it++) {
        int i = tid + it * 512;
        int row = i >> 4;
        int c4  = (i & 15) * 4;
        cp16(sB0 + (uint32_t)(row * SROW_B + c4) * 4, B + (size_t)row * D + c4, 16);
    }
    CP_COMMIT();
    CP_WAIT0();
    __syncthreads();

    const uint32_t aBase = sA + (uint32_t)(warp_m * 64) * SROW_A * 4;
    float acc[4][4][4];
#pragma unroll
    for (int mi = 0; mi < 4; mi++)
#pragma unroll
        for (int ni = 0; ni < 4; ni++)
#pragma unroll
            for (int f = 0; f < 4; f++) acc[mi][ni][f] = 0.f;

    for (int j = 0; j < 2; j++) {
        const uint32_t sCur = (j & 1) ? sB1 : sB0;
        if (j == 0) {
            const float* Bc = B + 64;
#pragma unroll
            for (int it = 0; it < 4; it++) {
                int i = tid + it * 512;
                int row = i >> 4;
                int c4  = (i & 15) * 4;
                cp16(sB1 + (uint32_t)(row * SROW_B + c4) * 4,
                     Bc + (size_t)row * D + c4, 16);
            }
            CP_COMMIT();
        }
        const int kbGlob = j * 64;
        const uint32_t bBase = sCur + (uint32_t)(warp_n * 32) * SROW_B * 4;
#pragma unroll
        for (int kc = 0; kc < 8; kc++) {
            const int kbA = kbGlob + kc * 8;
            const int kbB = kc * 8;
            uint32_t af[4][4], bf[4][2];
#pragma unroll
            for (int mi = 0; mi < 4; mi++) {
                uint32_t a0 = aBase + (uint32_t)((mi * 16 + g) * SROW_A + kbA + c) * 4;
                asm volatile("ld.shared.b32 %0, [%1];"    : "=r"(af[mi][0]) : "r"(a0));
                asm volatile("ld.shared.b32 %0, [%1+16];" : "=r"(af[mi][2]) : "r"(a0));
                uint32_t a1 = a0 + 8u * SROW_A * 4u;
                asm volatile("ld.shared.b32 %0, [%1];"    : "=r"(af[mi][1]) : "r"(a1));
                asm volatile("ld.shared.b32 %0, [%1+16];" : "=r"(af[mi][3]) : "r"(a1));
            }
#pragma unroll
            for (int ni = 0; ni < 4; ni++) {
                uint32_t b0 = bBase + (uint32_t)((ni * 8 + g) * SROW_B + kbB + c) * 4;
                asm volatile("ld.shared.b32 %0, [%1];"    : "=r"(bf[ni][0]) : "r"(b0));
                asm volatile("ld.shared.b32 %0, [%1+16];" : "=r"(bf[ni][1]) : "r"(b0));
            }
#pragma unroll
            for (int mi = 0; mi < 4; mi++)
#pragma unroll
                for (int ni = 0; ni < 4; ni++) {
                    asm volatile(
                        "mma.sync.aligned.m16n8k8.row.col.f32.tf32.tf32.f32 "
                        "{%0,%1,%2,%3}, {%4,%5,%6,%7}, {%8,%9}, {%0,%1,%2,%3};\n"
                        : "+f"(acc[mi][ni][0]), "+f"(acc[mi][ni][1]),
                          "+f"(acc[mi][ni][2]), "+f"(acc[mi][ni][3])
                        : "r"(af[mi][0]), "r"(af[mi][1]),
                          "r"(af[mi][2]), "r"(af[mi][3]),
                          "r"(bf[ni][0]), "r"(bf[ni][1]));
                }
        }
        if (j == 0) { CP_WAIT0(); __syncthreads(); }
    }

#pragma unroll
    for (int mi = 0; mi < 4; mi++) {
        const int row0 = mBase + warp_m * 64 + mi * 16 + g;
        const int row1 = row0 + 8;
#pragma unroll
        for (int ni = 0; ni < 4; ni++) {
            const int col = warp_n * 32 + ni * 8 + c * 2;
            float bx = bias[col], by = bias[col + 1];
            if (row0 < M)
                *(float2*)(C0 + (size_t)row0 * D + col) =
                    make_float2(acc[mi][ni][0] + bx, acc[mi][ni][1] + by);
            if (row1 < M)
                *(float2*)(C0 + (size_t)row1 * D + col) =
                    make_float2(acc[mi][ni][2] + bx, acc[mi][ni][3] + by);
        }
    }
}

// ---------------------------------------------------------------------------
// preprocessing: bucket edges by (rel, src>>7)
// ---------------------------------------------------------------------------
__global__ void hist_kernel(const int* __restrict__ src, const int* __restrict__ rel,
                            int E, int NT)
{
    int e = blockIdx.x * blockDim.x + threadIdx.x;
    if (e >= E) return;
    int key = rel[e] * NT + (src[e] >> 7);
    atomicAdd(&g_cnt[key], 1);
}

__global__ void scan_kernel(int nb)
{
    __shared__ int part[1024];
    const int tid = threadIdx.x;
    const int per = (nb + 1023) / 1024;
    const int base = tid * per;
    int s = 0;
    for (int i = 0; i < per; i++)
        if (base + i < nb) s += g_cnt[base + i];
    part[tid] = s;
    __syncthreads();
    for (int off = 1; off < 1024; off <<= 1) {
        int v = (tid >= off) ? part[tid - off] : 0;
        __syncthreads();
        part[tid] += v;
        __syncthreads();
    }
    int run = (tid > 0) ? part[tid - 1] : 0;
    for (int i = 0; i < per; i++) {
        if (base + i < nb) {
            g_rp[base + i] = run;
            run += g_cnt[base + i];
        }
    }
    if (tid == 1023) g_rp[nb] = part[1023];
}

__global__ void fill_kernel(const int* __restrict__ src, const int* __restrict__ rel,
                            int E, int NT)
{
    int e = blockIdx.x * blockDim.x + threadIdx.x;
    if (e >= E) return;
    int key = rel[e] * NT + (src[e] >> 7);
    int pos = g_rp[key] + atomicAdd(&g_cur[key], 1);
    g_perm[pos] = e;
}

// ---------------------------------------------------------------------------
__global__ void round_kernel(const float* __restrict__ x, float* __restrict__ y,
                             size_t n)
{
    size_t i = (size_t)blockIdx.x * blockDim.x + threadIdx.x;
    if (i < n) y[i] = f2tf32f(x[i]);
}

__global__ void round_wT_kernel(const float* __restrict__ W,
                                float* __restrict__ out, int R)
{
    int i = blockIdx.x * blockDim.x + threadIdx.x;
    if (i >= R * D * D) return;
    int r = i / (D * D);
    int e = (i / D) & (D - 1);
    int d = i & (D - 1);
    out[i] = f2tf32f(W[(size_t)r * D * D + (size_t)d * D + e]);
}

__global__ void glog_kernel(const float* __restrict__ h, const float* __restrict__ gw,
                            int Nn)
{
    int warp = (int)((blockIdx.x * blockDim.x + threadIdx.x) >> 5);
    int lane = threadIdx.x & 31;
    if (warp >= Nn) return;
    float4 hv = ((const float4*)(h + (size_t)warp * D))[lane];
    float mine = 0.f;
#pragma unroll
    for (int r = 0; r < NRELS; r++) {
        float4 gv = ((const float4*)(gw + r * D))[lane];
        float dot = hv.x * gv.x + hv.y * gv.y + hv.z * gv.z + hv.w * gv.w;
#pragma unroll
        for (int off = 16; off > 0; off >>= 1)
            dot += __shfl_down_sync(0xffffffffu, dot, off);
        dot = __shfl_sync(0xffffffffu, dot, 0);
        if (lane == r) mine = dot;
    }
    if (lane < NRELS) g_glog[(size_t)warp * NRELS + lane] = mine;
}

__global__ void relu_kernel(float* __restrict__ x, size_t n)
{
    size_t i = (size_t)blockIdx.x * blockDim.x + threadIdx.x;
    if (i < n) x[i] = fmaxf(x[i], 0.f);
}

// ---------------------------------------------------------------------------
static void run_layer(const float* hin, const float* W, const float* bias,
                      const float* lw, const float* gw,
                      const int* src, const int* dst, const int* rel,
                      const float* norm, float* hout,
                      float* atf, float* wt, float* lwt,
                      int Nn, int E, int NT, bool apply_relu)
{
    const size_t nElem = (size_t)Nn * D;

    round_kernel<<<(int)((nElem + 255) / 256), 256>>>(hin, atf, nElem);
    round_wT_kernel<<<(NRELS * D * D + 255) / 256, 256>>>(W, wt, NRELS);
    round_wT_kernel<<<(D * D + 255) / 256, 256>>>(lw, lwt, 1);
    glog_kernel<<<(Nn * 32 + 255) / 256, 256>>>(hin, gw, Nn);

    // out = h @ loop_w + bias  (accumulation target)
    gemm_loop<<<(Nn + 255) / 256, 512, GEMM_SMEM>>>(atf, lwt, hout, Nn, bias);

    // fused: hall GEMM + edge scatter, no intermediate buffer
    fused_gemm_scatter<<<NT, 256, FUSED_SMEM>>>(atf, wt, src, dst, rel, norm,
                                                hout, NT, Nn);

    if (apply_relu)
        relu_kernel<<<(int)((nElem + 255) / 256), 256>>>(hout, nElem);
}

extern "C" void kernel_launch(void* const* d_in, const int* in_sizes, int n_in,
                              void* d_out, int out_size)
{
    const float* h    = (const float*)d_in[0];
    const float* norm = (const float*)d_in[1];
    const float* W0   = (const float*)d_in[2];
    const float* b0   = (const float*)d_in[3];
    const float* lw0  = (const float*)d_in[4];
    const float* gw0  = (const float*)d_in[5];
    const float* W1   = (const float*)d_in[6];
    const float* b1   = (const float*)d_in[7];
    const float* lw1  = (const float*)d_in[8];
    const float* gw1  = (const float*)d_in[9];
    const int*   src  = (const int*)d_in[10];
    const int*   dst  = (const int*)d_in[11];
    const int*   rel  = (const int*)d_in[12];
    float* out = (float*)d_out;

    int Nn = in_sizes[0] / D;
    int E  = in_sizes[10];
    int NT = (Nn + 127) / 128;

    cudaFuncSetAttribute(fused_gemm_scatter,
                         cudaFuncAttributeMaxDynamicSharedMemorySize, FUSED_SMEM);
    cudaFuncSetAttribute(gemm_loop,
                         cudaFuncAttributeMaxDynamicSharedMemorySize, GEMM_SMEM);

    float *h1_ptr, *atf, *wt, *lwt;
    int *cnt, *cur;
    cudaGetSymbolAddress((void**)&h1_ptr, g_h1);
    cudaGetSymbolAddress((void**)&atf, g_atf);
    cudaGetSymbolAddress((void**)&wt, g_wt);
    cudaGetSymbolAddress((void**)&lwt, g_lwt);
    cudaGetSymbolAddress((void**)&cnt, g_cnt);
    cudaGetSymbolAddress((void**)&cur, g_cur);

    // ---- preprocess: bucket edges by (rel, src tile); reused by both layers
    cudaMemsetAsync(cnt, 0, NBMAX * sizeof(int));
    cudaMemsetAsync(cur, 0, NBMAX * sizeof(int));
    hist_kernel<<<(E + 255) / 256, 256>>>(src, rel, E, NT);
    scan_kernel<<<1, 1024>>>(NRELS * NT);
    fill_kernel<<<(E + 255) / 256, 256>>>(src, rel, E, NT);

    run_layer(h, W0, b0, lw0, gw0, src, dst, rel, norm, h1_ptr,
              atf, wt, lwt, Nn, E, NT, true);
    run_layer(h1_ptr, W1, b1, lw1, gw1, src, dst, rel, norm, out,
              atf, wt, lwt, Nn, E, NT, false);
}

// round 10
// speedup vs baseline: 1.7549x; 1.7549x over previous
#include <cuda_runtime.h>
#include <math.h>
#include <stdint.h>

#define D 128
#define NRELS 16
#define MAXN 50000
#define MAXE 800000

// ---------------- scratch (__device__ globals: allocation-free rule) -------
__device__ float g_hall[(size_t)NRELS * MAXN * D];   // [r][n][d]
__device__ float g_glog[(size_t)MAXN * NRELS];       // [n][r]  (pk = s*16+r)
__device__ float g_h1[(size_t)MAXN * D];             // layer-0 out
__device__ float g_hloop[(size_t)MAXN * D];          // self-loop + bias
__device__ float g_atf[(size_t)MAXN * D];            // layer input, tf32-rounded
__device__ float g_wt[(size_t)NRELS * D * D];        // W^T tf32-rounded [r][e][d]
__device__ float g_lwt[(size_t)D * D];               // loop_w^T tf32-rounded
__device__ int   g_dcnt[MAXN];                        // per-dst counts
__device__ int   g_dcur[MAXN];                        // per-dst cursors
__device__ int   g_drp[MAXN + 1];                     // dst CSR rowptr
__device__ int   g_spk[MAXE];                         // sorted packed src*16+rel
__device__ float g_snorm[MAXE];                       // sorted norm

__device__ __forceinline__ float f2tf32f(float x) {
    uint32_t y;
    asm("cvt.rna.tf32.f32 %0, %1;" : "=r"(y) : "f"(x));
    return __uint_as_float(y);
}
__device__ __forceinline__ uint32_t smem_u32(const void* p) {
    uint32_t a;
    asm("{ .reg .u64 t; cvta.to.shared.u64 t, %1; cvt.u32.u64 %0, t; }"
        : "=r"(a) : "l"(p));
    return a;
}
__device__ __forceinline__ void cp16(uint32_t dst, const void* src, int srcBytes) {
    asm volatile("cp.async.cg.shared.global [%0], [%1], 16, %2;"
                 :: "r"(dst), "l"(src), "r"(srcBytes) : "memory");
}
#define CP_COMMIT() asm volatile("cp.async.commit_group;" ::: "memory")
#define CP_WAIT0()  asm volatile("cp.async.wait_group 0;" ::: "memory")

#define SROW_A 132
#define SROW_B 68
#define SM_A_BYTES (256 * SROW_A * 4)     // 135168
#define SM_BCHUNK  (128 * SROW_B * 4)     // 34816
#define GEMM_SMEM  (SM_A_BYTES + 2 * SM_BCHUNK)   // 204800

// ---------------------------------------------------------------------------
// tf32 GEMM (R5 config, best measured): 512 threads, BM=256, BN=128,
// warp tile 64x32 (16 warps: 4m x 4n). Relation-looped, B double-buffered
// in half-K chunks via cp.async.
// ---------------------------------------------------------------------------
__global__ __launch_bounds__(512)
void gemm_v2(const float* __restrict__ A, const float* __restrict__ B,
             float* __restrict__ C0, size_t strideC, int Rper, int M,
             const float* __restrict__ bias)
{
    extern __shared__ char smem[];
    const uint32_t sA  = smem_u32(smem);
    const uint32_t sB0 = sA + SM_A_BYTES;
    const uint32_t sB1 = sB0 + SM_BCHUNK;

    const int tid  = threadIdx.x;
    const int lane = tid & 31;
    const int wid  = tid >> 5;
    const int warp_m = wid >> 2;
    const int warp_n = wid & 3;
    const int g = lane >> 2;
    const int c = lane & 3;
    const int mBase = blockIdx.x * 256;
    const int rBase = blockIdx.y * Rper;
    const int nChunks = 2 * Rper;

#pragma unroll
    for (int it = 0; it < 16; it++) {
        int i = tid + it * 512;
        int row = i >> 5;
        int c4  = (i & 31) * 4;
        bool valid = (mBase + row) < M;
        const float* src = A + (valid ? ((size_t)(mBase + row) * D + c4) : 0);
        cp16(sA + (uint32_t)(row * SROW_A + c4) * 4, src, valid ? 16 : 0);
    }
    {
        const float* Bc = B + (size_t)rBase * D * D;
#pragma unroll
        for (int it = 0; it < 4; it++) {
            int i = tid + it * 512;
            int row = i >> 4;
            int c4  = (i & 15) * 4;
            cp16(sB0 + (uint32_t)(row * SROW_B + c4) * 4,
                 Bc + (size_t)row * D + c4, 16);
        }
    }
    CP_COMMIT();
    CP_WAIT0();
    __syncthreads();

    const uint32_t aBase = sA + (uint32_t)(warp_m * 64) * SROW_A * 4;
    float acc[4][4][4];

    for (int j = 0; j < nChunks; j++) {
        const uint32_t sCur = (j & 1) ? sB1 : sB0;

        if (j + 1 < nChunks) {
            const uint32_t sNxt = (j & 1) ? sB0 : sB1;
            const int r1 = rBase + ((j + 1) >> 1);
            const int h1 = ((j + 1) & 1) * 64;
            const float* Bc = B + (size_t)r1 * D * D + h1;
#pragma unroll
            for (int it = 0; it < 4; it++) {
                int i = tid + it * 512;
                int row = i >> 4;
                int c4  = (i & 15) * 4;
                cp16(sNxt + (uint32_t)(row * SROW_B + c4) * 4,
                     Bc + (size_t)row * D + c4, 16);
            }
            CP_COMMIT();
        }

        if (!(j & 1)) {
#pragma unroll
            for (int mi = 0; mi < 4; mi++)
#pragma unroll
                for (int ni = 0; ni < 4; ni++)
#pragma unroll
                    for (int f = 0; f < 4; f++) acc[mi][ni][f] = 0.f;
        }

        const int kbGlob = (j & 1) * 64;
        const uint32_t bBase = sCur + (uint32_t)(warp_n * 32) * SROW_B * 4;
#pragma unroll
        for (int kc = 0; kc < 8; kc++) {
            const int kbA = kbGlob + kc * 8;
            const int kbB = kc * 8;
            uint32_t af[4][4], bf[4][2];
#pragma unroll
            for (int mi = 0; mi < 4; mi++) {
                uint32_t a0 = aBase + (uint32_t)((mi * 16 + g) * SROW_A + kbA + c) * 4;
                asm volatile("ld.shared.b32 %0, [%1];"    : "=r"(af[mi][0]) : "r"(a0));
                asm volatile("ld.shared.b32 %0, [%1+16];" : "=r"(af[mi][2]) : "r"(a0));
                uint32_t a1 = a0 + 8u * SROW_A * 4u;
                asm volatile("ld.shared.b32 %0, [%1];"    : "=r"(af[mi][1]) : "r"(a1));
                asm volatile("ld.shared.b32 %0, [%1+16];" : "=r"(af[mi][3]) : "r"(a1));
            }
#pragma unroll
            for (int ni = 0; ni < 4; ni++) {
                uint32_t b0 = bBase + (uint32_t)((ni * 8 + g) * SROW_B + kbB + c) * 4;
                asm volatile("ld.shared.b32 %0, [%1];"    : "=r"(bf[ni][0]) : "r"(b0));
                asm volatile("ld.shared.b32 %0, [%1+16];" : "=r"(bf[ni][1]) : "r"(b0));
            }
#pragma unroll
            for (int mi = 0; mi < 4; mi++)
#pragma unroll
                for (int ni = 0; ni < 4; ni++) {
                    asm volatile(
                        "mma.sync.aligned.m16n8k8.row.col.f32.tf32.tf32.f32 "
                        "{%0,%1,%2,%3}, {%4,%5,%6,%7}, {%8,%9}, {%0,%1,%2,%3};\n"
                        : "+f"(acc[mi][ni][0]), "+f"(acc[mi][ni][1]),
                          "+f"(acc[mi][ni][2]), "+f"(acc[mi][ni][3])
                        : "r"(af[mi][0]), "r"(af[mi][1]),
                          "r"(af[mi][2]), "r"(af[mi][3]),
                          "r"(bf[ni][0]), "r"(bf[ni][1]));
                }
        }

        if (j & 1) {
            const int r = rBase + (j >> 1);
            float* C = C0 + (size_t)r * strideC;
#pragma unroll
            for (int mi = 0; mi < 4; mi++) {
                const int row0 = mBase + warp_m * 64 + mi * 16 + g;
                const int row1 = row0 + 8;
#pragma unroll
                for (int ni = 0; ni < 4; ni++) {
                    const int col = warp_n * 32 + ni * 8 + c * 2;
                    float bx = 0.f, by = 0.f;
                    if (bias != nullptr) { bx = bias[col]; by = bias[col + 1]; }
                    if (row0 < M)
                        *(float2*)(C + (size_t)row0 * D + col) =
                            make_float2(acc[mi][ni][0] + bx, acc[mi][ni][1] + by);
                    if (row1 < M)
                        *(float2*)(C + (size_t)row1 * D + col) =
                            make_float2(acc[mi][ni][2] + bx, acc[mi][ni][3] + by);
                }
            }
        }

        if (j + 1 < nChunks) {
            CP_WAIT0();
            __syncthreads();
        }
    }
}

// ---------------------------------------------------------------------------
// dst-CSR build: hist -> scan -> fill (packed sorted edge meta)
// ---------------------------------------------------------------------------
__global__ void hist_kernel(const int* __restrict__ dst, int E)
{
    int e = blockIdx.x * blockDim.x + threadIdx.x;
    if (e < E) atomicAdd(&g_dcnt[dst[e]], 1);
}

__global__ void scan_kernel(int nb)
{
    __shared__ int part[1024];
    const int tid = threadIdx.x;
    const int per = (nb + 1023) / 1024;
    const int base = tid * per;
    int s = 0;
    for (int i = 0; i < per; i++)
        if (base + i < nb) s += g_dcnt[base + i];
    part[tid] = s;
    __syncthreads();
    for (int off = 1; off < 1024; off <<= 1) {
        int v = (tid >= off) ? part[tid - off] : 0;
        __syncthreads();
        part[tid] += v;
        __syncthreads();
    }
    int run = (tid > 0) ? part[tid - 1] : 0;
    for (int i = 0; i < per; i++) {
        if (base + i < nb) {
            g_drp[base + i] = run;
            run += g_dcnt[base + i];
        }
    }
    if (tid == 1023) g_drp[nb] = part[1023];
}

__global__ void fill_kernel(const int* __restrict__ src, const int* __restrict__ dst,
                            const int* __restrict__ rel, const float* __restrict__ norm,
                            int E)
{
    int e = blockIdx.x * blockDim.x + threadIdx.x;
    if (e >= E) return;
    int d = dst[e];
    int pos = g_drp[d] + atomicAdd(&g_dcur[d], 1);
    g_spk[pos] = src[e] * NRELS + rel[e];
    g_snorm[pos] = norm[e];
}

// ---------------------------------------------------------------------------
// Gather: one warp per dst node. out[n] = sum_in-edges gate*norm*hall_row
//         + hloop[n] (has bias). Optional relu; optional tf32-rounded copy.
// ---------------------------------------------------------------------------
__global__ void gather_kernel(float* __restrict__ out, float* __restrict__ out_tf,
                              int Nn, int apply_relu)
{
    int n = (int)((blockIdx.x * blockDim.x + threadIdx.x) >> 5);
    int lane = threadIdx.x & 31;
    if (n >= Nn) return;

    const int e0 = g_drp[n], e1 = g_drp[n + 1];

    float4 acc = ((const float4*)(g_hloop + (size_t)n * D))[lane];

    for (int i0 = e0; i0 < e1; i0 += 32) {
        int cnt = min(32, e1 - i0);
        int pk = 0; float nm = 0.f;
        if (lane < cnt) {
            pk = g_spk[i0 + lane];
            nm = g_snorm[i0 + lane];
        }
        for (int j = 0; j < cnt; j++) {
            int pkj = __shfl_sync(0xffffffffu, pk, j);
            float nmj = __shfl_sync(0xffffffffu, nm, j);
            float gl = g_glog[pkj];
            float gc = nmj / (1.f + expf(-gl));
            int s = pkj >> 4;       // NRELS == 16
            int r = pkj & 15;
            float4 v = ((const float4*)(g_hall + ((size_t)r * Nn + s) * D))[lane];
            acc.x += gc * v.x; acc.y += gc * v.y;
            acc.z += gc * v.z; acc.w += gc * v.w;
        }
    }

    if (apply_relu) {
        acc.x = fmaxf(acc.x, 0.f); acc.y = fmaxf(acc.y, 0.f);
        acc.z = fmaxf(acc.z, 0.f); acc.w = fmaxf(acc.w, 0.f);
    }
    ((float4*)(out + (size_t)n * D))[lane] = acc;
    if (out_tf != nullptr) {
        float4 t;
        t.x = f2tf32f(acc.x); t.y = f2tf32f(acc.y);
        t.z = f2tf32f(acc.z); t.w = f2tf32f(acc.w);
        ((float4*)(out_tf + (size_t)n * D))[lane] = t;
    }
}

// ---------------------------------------------------------------------------
__global__ void round_kernel(const float* __restrict__ x, float* __restrict__ y,
                             size_t n)
{
    size_t i = (size_t)blockIdx.x * blockDim.x + threadIdx.x;
    if (i < n) y[i] = f2tf32f(x[i]);
}

__global__ void round_wT_kernel(const float* __restrict__ W,
                                float* __restrict__ out, int R)
{
    int i = blockIdx.x * blockDim.x + threadIdx.x;
    if (i >= R * D * D) return;
    int r = i / (D * D);
    int e = (i / D) & (D - 1);
    int d = i & (D - 1);
    out[i] = f2tf32f(W[(size_t)r * D * D + (size_t)d * D + e]);
}

__global__ void glog_kernel(const float* __restrict__ h, const float* __restrict__ gw,
                            int Nn)
{
    int warp = (int)((blockIdx.x * blockDim.x + threadIdx.x) >> 5);
    int lane = threadIdx.x & 31;
    if (warp >= Nn) return;
    float4 hv = ((const float4*)(h + (size_t)warp * D))[lane];
    float mine = 0.f;
#pragma unroll
    for (int r = 0; r < NRELS; r++) {
        float4 gv = ((const float4*)(gw + r * D))[lane];
        float dot = hv.x * gv.x + hv.y * gv.y + hv.z * gv.z + hv.w * gv.w;
#pragma unroll
        for (int off = 16; off > 0; off >>= 1)
            dot += __shfl_down_sync(0xffffffffu, dot, off);
        dot = __shfl_sync(0xffffffffu, dot, 0);
        if (lane == r) mine = dot;
    }
    if (lane < NRELS) g_glog[(size_t)warp * NRELS + lane] = mine;
}

// ---------------------------------------------------------------------------
static void run_layer(const float* hinfp, const float* atf_in,
                      const float* W, const float* bias,
                      const float* lw, const float* gw,
                      float* hall_ptr, float* hloop_ptr,
                      float* hout, float* hout_tf,
                      float* wt, float* lwt,
                      int Nn, int E, bool apply_relu)
{
    const int mtiles = (Nn + 255) / 256;

    round_wT_kernel<<<(NRELS * D * D + 255) / 256, 256>>>(W, wt, NRELS);
    round_wT_kernel<<<(D * D + 255) / 256, 256>>>(lw, lwt, 1);
    glog_kernel<<<(Nn * 32 + 255) / 256, 256>>>(hinfp, gw, Nn);

    // hloop = h @ loop_w + bias
    gemm_v2<<<dim3(mtiles, 1), 512, GEMM_SMEM>>>(atf_in, lwt, hloop_ptr,
                                                 0, 1, Nn, bias);
    // hall[r] = h @ W[r]
    gemm_v2<<<dim3(mtiles, 2), 512, GEMM_SMEM>>>(atf_in, wt, hall_ptr,
                                                 (size_t)Nn * D, NRELS / 2, Nn,
                                                 nullptr);
    // gather: out[n] = sum_msgs + hloop[n]  (+relu, +tf32 copy)
    gather_kernel<<<(Nn * 32 + 255) / 256, 256>>>(hout, hout_tf, Nn,
                                                  apply_relu ? 1 : 0);
}

extern "C" void kernel_launch(void* const* d_in, const int* in_sizes, int n_in,
                              void* d_out, int out_size)
{
    const float* h    = (const float*)d_in[0];
    const float* norm = (const float*)d_in[1];
    const float* W0   = (const float*)d_in[2];
    const float* b0   = (const float*)d_in[3];
    const float* lw0  = (const float*)d_in[4];
    const float* gw0  = (const float*)d_in[5];
    const float* W1   = (const float*)d_in[6];
    const float* b1   = (const float*)d_in[7];
    const float* lw1  = (const float*)d_in[8];
    const float* gw1  = (const float*)d_in[9];
    const int*   src  = (const int*)d_in[10];
    const int*   dst  = (const int*)d_in[11];
    const int*   rel  = (const int*)d_in[12];
    float* out = (float*)d_out;

    int Nn = in_sizes[0] / D;
    int E  = in_sizes[10];

    cudaFuncSetAttribute(gemm_v2, cudaFuncAttributeMaxDynamicSharedMemorySize,
                         GEMM_SMEM);

    float *hall_ptr, *h1_ptr, *hloop_ptr, *atf, *wt, *lwt;
    int *dcnt, *dcur;
    cudaGetSymbolAddress((void**)&hall_ptr, g_hall);
    cudaGetSymbolAddress((void**)&h1_ptr, g_h1);
    cudaGetSymbolAddress((void**)&hloop_ptr, g_hloop);
    cudaGetSymbolAddress((void**)&atf, g_atf);
    cudaGetSymbolAddress((void**)&wt, g_wt);
    cudaGetSymbolAddress((void**)&lwt, g_lwt);
    cudaGetSymbolAddress((void**)&dcnt, g_dcnt);
    cudaGetSymbolAddress((void**)&dcur, g_dcur);

    // ---- preprocess (shared by both layers) --------------------------------
    cudaMemsetAsync(dcnt, 0, Nn * sizeof(int));
    cudaMemsetAsync(dcur, 0, Nn * sizeof(int));
    hist_kernel<<<(E + 255) / 256, 256>>>(dst, E);
    scan_kernel<<<1, 1024>>>(Nn);
    fill_kernel<<<(E + 255) / 256, 256>>>(src, dst, rel, norm, E);

    // layer-0 input rounded to tf32
    size_t nElem = (size_t)Nn * D;
    round_kernel<<<(int)((nElem + 255) / 256), 256>>>(h, atf, nElem);

    // Layer 0: relu; writes h1 (fp32) and atf (tf32) for layer 1
    run_layer(h, atf, W0, b0, lw0, gw0, hall_ptr, hloop_ptr,
              h1_ptr, atf, wt, lwt, Nn, E, true);
    // Layer 1: no relu, writes final output
    run_layer(h1_ptr, atf, W1, b1, lw1, gw1, hall_ptr, hloop_ptr,
              out, nullptr, wt, lwt, Nn, E, false);
}